// round 1
// baseline (speedup 1.0000x reference)
#include <cuda_runtime.h>
#include <math.h>

#define NMAX 50048
#define EMAX 800032
#define SLOPE 0.2f

// ---- scratch (no allocs allowed) ----
__device__ float g_h[(size_t)NMAX * 128];   // transformed features
__device__ float g_as[NMAX];                // src logits
__device__ float g_ad[NMAX];                // dst logits
__device__ float g_den[NMAX];               // softmax denominators
__device__ float g_p[EMAX];                 // per-edge exp(e)
__device__ int   g_src[EMAX];
__device__ int   g_dst[EMAX];
__device__ int   g_is64;

// ============================================================
// K0: detect whether edge_index buffer is int64 or int32
// (int32 data read as int64 -> values >= 2^32 w.h.p.)
// ============================================================
__global__ void detect_kernel(const long long* __restrict__ ei, int E, int N) {
    __shared__ int bad;
    if (threadIdx.x == 0) bad = 0;
    __syncthreads();
    int i = threadIdx.x;
    if (i < E) {
        long long v = ei[i];
        if (v < 0 || v >= (long long)N) atomicOr(&bad, 1);
    }
    __syncthreads();
    if (threadIdx.x == 0) g_is64 = bad ? 0 : 1;
}

// ============================================================
// K1: h = x @ W  (fp32, 128x128 block tile, 8x8 microtile)
// ============================================================
__global__ __launch_bounds__(256, 2)
void gemm128(const float* __restrict__ x, const float* __restrict__ W, int N) {
    __shared__ float xs[32][132];  // transposed x tile: xs[k][row]
    __shared__ float ws[32][132];  // ws[k][col]

    int tid = threadIdx.x;
    int tx = tid & 15;   // col group
    int ty = tid >> 4;   // row group
    int rowBase = blockIdx.x * 128;

    float acc[8][8];
#pragma unroll
    for (int i = 0; i < 8; i++)
#pragma unroll
        for (int j = 0; j < 8; j++) acc[i][j] = 0.f;

    for (int kc = 0; kc < 128; kc += 32) {
        // load x tile (128 rows x 32 k) transposed into smem
#pragma unroll
        for (int it = 0; it < 4; it++) {
            int v = tid + it * 256;        // 0..1023 float4 slots
            int r = v >> 3;                // 0..127
            int kq = v & 7;                // 0..7 (float4 along k)
            int gr = rowBase + r;
            float4 xv = make_float4(0.f, 0.f, 0.f, 0.f);
            if (gr < N) xv = *(const float4*)&x[(size_t)gr * 128 + kc + kq * 4];
            xs[kq * 4 + 0][r] = xv.x;
            xs[kq * 4 + 1][r] = xv.y;
            xs[kq * 4 + 2][r] = xv.z;
            xs[kq * 4 + 3][r] = xv.w;
        }
        // load W chunk (32 k x 128 cols)
#pragma unroll
        for (int it = 0; it < 4; it++) {
            int v = tid + it * 256;
            int k = v >> 5;                // 0..31
            int nq = v & 31;               // 0..31 (float4 along n)
            float4 wv = *(const float4*)&W[(size_t)(kc + k) * 128 + nq * 4];
            *(float4*)&ws[k][nq * 4] = wv;
        }
        __syncthreads();

#pragma unroll
        for (int k = 0; k < 32; k++) {
            float a[8], b[8];
            *(float4*)&a[0] = *(const float4*)&xs[k][ty * 8];
            *(float4*)&a[4] = *(const float4*)&xs[k][ty * 8 + 4];
            *(float4*)&b[0] = *(const float4*)&ws[k][tx * 8];
            *(float4*)&b[4] = *(const float4*)&ws[k][tx * 8 + 4];
#pragma unroll
            for (int i = 0; i < 8; i++)
#pragma unroll
                for (int j = 0; j < 8; j++)
                    acc[i][j] += a[i] * b[j];
        }
        __syncthreads();
    }

#pragma unroll
    for (int i = 0; i < 8; i++) {
        int gr = rowBase + ty * 8 + i;
        if (gr < N) {
            *(float4*)&g_h[(size_t)gr * 128 + tx * 8] =
                make_float4(acc[i][0], acc[i][1], acc[i][2], acc[i][3]);
            *(float4*)&g_h[(size_t)gr * 128 + tx * 8 + 4] =
                make_float4(acc[i][4], acc[i][5], acc[i][6], acc[i][7]);
        }
    }
}

// ============================================================
// K2: per-node logits a_s, a_d; init denom with self-loop term
// one warp per node
// ============================================================
__global__ void node_logits(const float* __restrict__ att_s,
                            const float* __restrict__ att_d, int N) {
    int warp = (blockIdx.x * blockDim.x + threadIdx.x) >> 5;
    int lane = threadIdx.x & 31;
    if (warp >= N) return;
    float4 hv = *(const float4*)&g_h[(size_t)warp * 128 + lane * 4];
    float4 s4 = *(const float4*)&att_s[lane * 4];
    float4 d4 = *(const float4*)&att_d[lane * 4];
    float s = hv.x * s4.x + hv.y * s4.y + hv.z * s4.z + hv.w * s4.w;
    float d = hv.x * d4.x + hv.y * d4.y + hv.z * d4.z + hv.w * d4.w;
#pragma unroll
    for (int o = 16; o > 0; o >>= 1) {
        s += __shfl_xor_sync(0xffffffffu, s, o);
        d += __shfl_xor_sync(0xffffffffu, d, o);
    }
    if (lane == 0) {
        g_as[warp] = s;
        g_ad[warp] = d;
        float e = s + d;
        e = e > 0.f ? e : SLOPE * e;
        g_den[warp] = expf(e);  // self-loop contribution
    }
}

// ============================================================
// K3: per-edge: decode indices (int64 or int32), compute p,
// accumulate denom
// ============================================================
__global__ void edge_prep(const long long* __restrict__ ei, int E) {
    int e = blockIdx.x * blockDim.x + threadIdx.x;
    if (e >= E) return;
    int s, d;
    if (g_is64) {
        s = (int)ei[e];
        d = (int)ei[(size_t)E + e];
    } else {
        const int* p32 = (const int*)ei;
        s = p32[e];
        d = p32[E + e];
    }
    g_src[e] = s;
    g_dst[e] = d;
    float v = g_as[s] + g_ad[d];
    v = v > 0.f ? v : SLOPE * v;
    float pe = expf(v);
    g_p[e] = pe;
    atomicAdd(&g_den[d], pe);
}

// ============================================================
// K4: init out with bias + self-loop contribution
// ============================================================
__global__ void out_init(float* __restrict__ out, const float* __restrict__ bias,
                         int N) {
    int idx = blockIdx.x * blockDim.x + threadIdx.x;  // float4 granularity
    if (idx >= N * 32) return;
    int node = idx >> 5;
    int q = idx & 31;
    float e = g_as[node] + g_ad[node];
    e = e > 0.f ? e : SLOPE * e;
    float w = expf(e) / g_den[node];
    float4 hv = *(const float4*)&g_h[(size_t)node * 128 + q * 4];
    float4 b = *(const float4*)&bias[q * 4];
    float4 o;
    o.x = b.x + hv.x * w;
    o.y = b.y + hv.y * w;
    o.z = b.z + hv.z * w;
    o.w = b.w + hv.w * w;
    *(float4*)&out[(size_t)node * 128 + q * 4] = o;
}

// ============================================================
// K5: edge scatter: out[dst] += alpha * h[src]; warp per 32 edges
// ============================================================
__global__ void edge_scatter(float* __restrict__ out, int E) {
    int warp = (blockIdx.x * blockDim.x + threadIdx.x) >> 5;
    int lane = threadIdx.x & 31;
    int e0 = warp * 32;
    if (e0 >= E) return;
    int e = e0 + lane;
    int s = 0, d = 0;
    float alpha = 0.f;
    if (e < E) {
        s = g_src[e];
        d = g_dst[e];
        alpha = g_p[e] / g_den[d];
    }
    int nv = E - e0;
    if (nv > 32) nv = 32;
#pragma unroll 1
    for (int j = 0; j < nv; j++) {
        int sj = __shfl_sync(0xffffffffu, s, j);
        int dj = __shfl_sync(0xffffffffu, d, j);
        float aj = __shfl_sync(0xffffffffu, alpha, j);
        float4 hv = *(const float4*)&g_h[(size_t)sj * 128 + lane * 4];
        float* addr = &out[(size_t)dj * 128 + lane * 4];
        asm volatile("red.global.add.v4.f32 [%0], {%1, %2, %3, %4};"
                     :: "l"(addr), "f"(hv.x * aj), "f"(hv.y * aj),
                        "f"(hv.z * aj), "f"(hv.w * aj)
                     : "memory");
    }
}

// ============================================================
extern "C" void kernel_launch(void* const* d_in, const int* in_sizes, int n_in,
                              void* d_out, int out_size) {
    const float*     x     = (const float*)d_in[0];
    const long long* ei    = (const long long*)d_in[1];
    const float*     W     = (const float*)d_in[2];
    const float*     att_s = (const float*)d_in[3];
    const float*     att_d = (const float*)d_in[4];
    const float*     bias  = (const float*)d_in[5];
    float*           out   = (float*)d_out;

    int N = in_sizes[0] / 128;
    int E = in_sizes[1] / 2;

    detect_kernel<<<1, 1024>>>(ei, E, N);
    gemm128<<<(N + 127) / 128, 256>>>(x, W, N);
    node_logits<<<(N + 7) / 8, 256>>>(att_s, att_d, N);
    edge_prep<<<(E + 255) / 256, 256>>>(ei, E);
    out_init<<<(N * 32 + 255) / 256, 256>>>(out, bias, N);
    edge_scatter<<<((E + 31) / 32 + 7) / 8, 256>>>(out, E);
}

// round 2
// speedup vs baseline: 1.2375x; 1.2375x over previous
#include <cuda_runtime.h>
#include <math.h>

#define NMAX 50048
#define EMAX 800032
#define SLOPE 0.2f

// ---- scratch (no allocs allowed) ----
__device__ float g_h[(size_t)NMAX * 128];   // transformed features
__device__ float g_as[NMAX];                // src logits
__device__ float g_ad[NMAX];                // dst logits
__device__ int   g_deg[NMAX];               // in-degree histogram
__device__ int   g_scan[NMAX];              // block-local exclusive scan
__device__ int   g_bt[256];                 // per-block totals
__device__ int   g_off[NMAX + 1];           // CSR offsets
__device__ int   g_cur[NMAX];               // fill cursors
__device__ int   g_eidx[EMAX];              // CSR: src index per slot
__device__ int   g_is64;

// ============================================================
// K0: detect whether edge_index buffer is int64 or int32
// ============================================================
__global__ void detect_kernel(const long long* __restrict__ ei, int E, int N) {
    __shared__ int bad;
    if (threadIdx.x == 0) bad = 0;
    __syncthreads();
    int i = threadIdx.x;
    if (i < E) {
        long long v = ei[i];
        if (v < 0 || v >= (long long)N) atomicOr(&bad, 1);
    }
    __syncthreads();
    if (threadIdx.x == 0) g_is64 = bad ? 0 : 1;
}

// ============================================================
// K1: h = x @ W  (fp32, 128x128 block tile, 8x8 microtile)
// ============================================================
__global__ __launch_bounds__(256, 2)
void gemm128(const float* __restrict__ x, const float* __restrict__ W, int N) {
    __shared__ float xs[32][132];
    __shared__ float ws[32][132];

    int tid = threadIdx.x;
    int tx = tid & 15;
    int ty = tid >> 4;
    int rowBase = blockIdx.x * 128;

    float acc[8][8];
#pragma unroll
    for (int i = 0; i < 8; i++)
#pragma unroll
        for (int j = 0; j < 8; j++) acc[i][j] = 0.f;

    for (int kc = 0; kc < 128; kc += 32) {
#pragma unroll
        for (int it = 0; it < 4; it++) {
            int v = tid + it * 256;
            int r = v >> 3;
            int kq = v & 7;
            int gr = rowBase + r;
            float4 xv = make_float4(0.f, 0.f, 0.f, 0.f);
            if (gr < N) xv = *(const float4*)&x[(size_t)gr * 128 + kc + kq * 4];
            xs[kq * 4 + 0][r] = xv.x;
            xs[kq * 4 + 1][r] = xv.y;
            xs[kq * 4 + 2][r] = xv.z;
            xs[kq * 4 + 3][r] = xv.w;
        }
#pragma unroll
        for (int it = 0; it < 4; it++) {
            int v = tid + it * 256;
            int k = v >> 5;
            int nq = v & 31;
            float4 wv = *(const float4*)&W[(size_t)(kc + k) * 128 + nq * 4];
            *(float4*)&ws[k][nq * 4] = wv;
        }
        __syncthreads();

#pragma unroll
        for (int k = 0; k < 32; k++) {
            float a[8], b[8];
            *(float4*)&a[0] = *(const float4*)&xs[k][ty * 8];
            *(float4*)&a[4] = *(const float4*)&xs[k][ty * 8 + 4];
            *(float4*)&b[0] = *(const float4*)&ws[k][tx * 8];
            *(float4*)&b[4] = *(const float4*)&ws[k][tx * 8 + 4];
#pragma unroll
            for (int i = 0; i < 8; i++)
#pragma unroll
                for (int j = 0; j < 8; j++)
                    acc[i][j] += a[i] * b[j];
        }
        __syncthreads();
    }

#pragma unroll
    for (int i = 0; i < 8; i++) {
        int gr = rowBase + ty * 8 + i;
        if (gr < N) {
            *(float4*)&g_h[(size_t)gr * 128 + tx * 8] =
                make_float4(acc[i][0], acc[i][1], acc[i][2], acc[i][3]);
            *(float4*)&g_h[(size_t)gr * 128 + tx * 8 + 4] =
                make_float4(acc[i][4], acc[i][5], acc[i][6], acc[i][7]);
        }
    }
}

// ============================================================
// K2: per-node logits a_s, a_d (warp per node); zero histogram
// ============================================================
__global__ void node_logits(const float* __restrict__ att_s,
                            const float* __restrict__ att_d, int N) {
    int warp = (blockIdx.x * blockDim.x + threadIdx.x) >> 5;
    int lane = threadIdx.x & 31;
    if (warp >= N) return;
    float4 hv = *(const float4*)&g_h[(size_t)warp * 128 + lane * 4];
    float4 s4 = *(const float4*)&att_s[lane * 4];
    float4 d4 = *(const float4*)&att_d[lane * 4];
    float s = hv.x * s4.x + hv.y * s4.y + hv.z * s4.z + hv.w * s4.w;
    float d = hv.x * d4.x + hv.y * d4.y + hv.z * d4.z + hv.w * d4.w;
#pragma unroll
    for (int o = 16; o > 0; o >>= 1) {
        s += __shfl_xor_sync(0xffffffffu, s, o);
        d += __shfl_xor_sync(0xffffffffu, d, o);
    }
    if (lane == 0) {
        g_as[warp] = s;
        g_ad[warp] = d;
        g_deg[warp] = 0;
    }
}

// ============================================================
// K3: in-degree histogram over dst
// ============================================================
__global__ void hist_kernel(const long long* __restrict__ ei, int E) {
    int e = blockIdx.x * blockDim.x + threadIdx.x;
    if (e >= E) return;
    int d;
    if (g_is64) d = (int)ei[(size_t)E + e];
    else        d = ((const int*)ei)[E + e];
    atomicAdd(&g_deg[d], 1);
}

// ============================================================
// K4a: block-local exclusive scan (256 per block) + block totals
// ============================================================
__global__ void scan_blocks(int N) {
    __shared__ int sh[256];
    int i = blockIdx.x * 256 + threadIdx.x;
    int v = (i < N) ? g_deg[i] : 0;
    sh[threadIdx.x] = v;
    __syncthreads();
#pragma unroll
    for (int o = 1; o < 256; o <<= 1) {
        int t = (threadIdx.x >= o) ? sh[threadIdx.x - o] : 0;
        __syncthreads();
        sh[threadIdx.x] += t;
        __syncthreads();
    }
    if (i < N) g_scan[i] = sh[threadIdx.x] - v;  // exclusive
    if (threadIdx.x == 255) g_bt[blockIdx.x] = sh[255];
}

// ============================================================
// K4b: scan the block totals (single block), set g_off[N]=E
// ============================================================
__global__ void scan_totals(int nb, int E, int N) {
    __shared__ int sh[256];
    int v = (threadIdx.x < nb) ? g_bt[threadIdx.x] : 0;
    sh[threadIdx.x] = v;
    __syncthreads();
#pragma unroll
    for (int o = 1; o < 256; o <<= 1) {
        int t = (threadIdx.x >= o) ? sh[threadIdx.x - o] : 0;
        __syncthreads();
        sh[threadIdx.x] += t;
        __syncthreads();
    }
    g_bt[threadIdx.x] = sh[threadIdx.x] - v;  // exclusive totals
    if (threadIdx.x == 0) g_off[N] = E;
}

// ============================================================
// K4c: add back -> CSR offsets + cursors
// ============================================================
__global__ void scan_addback(int N) {
    int i = blockIdx.x * 256 + threadIdx.x;
    if (i >= N) return;
    int o = g_scan[i] + g_bt[blockIdx.x];
    g_off[i] = o;
    g_cur[i] = o;
}

// ============================================================
// K5: fill CSR slots with src indices
// ============================================================
__global__ void fill_kernel(const long long* __restrict__ ei, int E) {
    int e = blockIdx.x * blockDim.x + threadIdx.x;
    if (e >= E) return;
    int s, d;
    if (g_is64) {
        s = (int)ei[e];
        d = (int)ei[(size_t)E + e];
    } else {
        const int* p32 = (const int*)ei;
        s = p32[e];
        d = p32[E + e];
    }
    int slot = atomicAdd(&g_cur[d], 1);
    g_eidx[slot] = s;
}

// ============================================================
// K6: fused softmax + aggregate: warp per dst node, no atomics.
// acc = p_self*h[node] + sum_e p_e*h[src_e]; out = acc/den + bias
// ============================================================
__global__ __launch_bounds__(256)
void aggregate(float* __restrict__ out, const float* __restrict__ bias, int N) {
    int node = (blockIdx.x * blockDim.x + threadIdx.x) >> 5;
    int lane = threadIdx.x & 31;
    if (node >= N) return;

    float ad = g_ad[node];
    float e0 = g_as[node] + ad;
    e0 = e0 > 0.f ? e0 : SLOPE * e0;
    float pself = expf(e0);

    float4 hv = *(const float4*)&g_h[(size_t)node * 128 + lane * 4];
    float4 acc;
    acc.x = pself * hv.x;
    acc.y = pself * hv.y;
    acc.z = pself * hv.z;
    acc.w = pself * hv.w;
    float den = pself;

    int beg = g_off[node];
    int end = g_off[node + 1];
    for (int base = beg; base < end; base += 32) {
        int e = base + lane;
        int s = (e < end) ? g_eidx[e] : 0;
        int nv = end - base;
        if (nv > 32) nv = 32;
#pragma unroll 4
        for (int j = 0; j < nv; j++) {
            int sj = __shfl_sync(0xffffffffu, s, j);
            float v = g_as[sj] + ad;
            v = v > 0.f ? v : SLOPE * v;
            float p = expf(v);
            float4 h4 = *(const float4*)&g_h[(size_t)sj * 128 + lane * 4];
            den += p;
            acc.x += p * h4.x;
            acc.y += p * h4.y;
            acc.z += p * h4.z;
            acc.w += p * h4.w;
        }
    }

    float inv = 1.f / den;
    float4 b = *(const float4*)&bias[lane * 4];
    float4 o;
    o.x = acc.x * inv + b.x;
    o.y = acc.y * inv + b.y;
    o.z = acc.z * inv + b.z;
    o.w = acc.w * inv + b.w;
    *(float4*)&out[(size_t)node * 128 + lane * 4] = o;
}

// ============================================================
extern "C" void kernel_launch(void* const* d_in, const int* in_sizes, int n_in,
                              void* d_out, int out_size) {
    const float*     x     = (const float*)d_in[0];
    const long long* ei    = (const long long*)d_in[1];
    const float*     W     = (const float*)d_in[2];
    const float*     att_s = (const float*)d_in[3];
    const float*     att_d = (const float*)d_in[4];
    const float*     bias  = (const float*)d_in[5];
    float*           out   = (float*)d_out;

    int N = in_sizes[0] / 128;
    int E = in_sizes[1] / 2;
    int nb = (N + 255) / 256;

    detect_kernel<<<1, 1024>>>(ei, E, N);
    gemm128<<<(N + 127) / 128, 256>>>(x, W, N);
    node_logits<<<(N + 7) / 8, 256>>>(att_s, att_d, N);
    hist_kernel<<<(E + 255) / 256, 256>>>(ei, E);
    scan_blocks<<<nb, 256>>>(N);
    scan_totals<<<1, 256>>>(nb, E, N);
    scan_addback<<<nb, 256>>>(N);
    fill_kernel<<<(E + 255) / 256, 256>>>(ei, E);
    aggregate<<<(N * 32 + 255) / 256, 256>>>(out, bias, N);
}